// round 1
// baseline (speedup 1.0000x reference)
#include <cuda_runtime.h>
#include <math.h>

#define BB     2
#define NN     128
#define EB     160
#define DEPTHL 6
#define NHEADS 8
#define DH     64
#define INNERD 512
#define DIMF   128
#define NF     127
#define SCALE  0.125f  /* 64^-0.5 */

// ---------------- scratch (static device globals; no allocation) -------------
__device__ float g_nodes[BB*NN*DIMF];
__device__ float g_edges[BB*NN*NN*3];
__device__ float g_q   [BB*NN*INNERD];
__device__ float g_kbe [BB*NN*INNERD];
__device__ float g_vbe [BB*NN*INNERD];
__device__ float g_qWe [BB*NN*NHEADS*3];
__device__ float g_ao  [BB*NN*INNERD];

// ---------------- helpers ----------------------------------------------------
__device__ __forceinline__ float blk_sum256(float v, float* sred) {
    int tid = threadIdx.x;
    #pragma unroll
    for (int off = 16; off > 0; off >>= 1)
        v += __shfl_xor_sync(0xffffffffu, v, off);
    __syncthreads();                    // protect previous read of sred
    if ((tid & 31) == 0) sred[tid >> 5] = v;
    __syncthreads();
    if (tid == 0) {
        float t = 0.f;
        #pragma unroll
        for (int w = 0; w < 8; w++) t += sred[w];
        sred[0] = t;
    }
    __syncthreads();
    return sred[0];
}

// ---------------- prologue ----------------------------------------------------
__global__ void k_init(const int* __restrict__ indices,
                       const float* __restrict__ atom_emb,
                       const float* __restrict__ noise)
{
    int idx = blockIdx.x * blockDim.x + threadIdx.x;
    int stride = gridDim.x * blockDim.x;
    for (int t = idx; t < BB*NN*DIMF; t += stride) {
        int f  = t % DIMF;
        int bn = t / DIMF;
        g_nodes[t] = (f < NF) ? atom_emb[indices[bn] * NF + f] : noise[0];
    }
    for (int t = idx; t < BB*NN*NN*3; t += stride) g_edges[t] = 0.f;
}

// Sequential scatter matching JAX .at[].set ordering (phase1 fully, then phase2),
// parallel only over (b,c) which never collide.
__global__ void k_edges(const int* __restrict__ bonds,
                        const float* __restrict__ coords)
{
    int lane = threadIdx.x;
    if (blockIdx.x != 0 || lane >= BB*3) return;
    int b = lane / 3, c = lane % 3;
    for (int e = 0; e < EB; e++) {
        int i = bonds[2*e], j = bonds[2*e+1];
        float d = coords[(b*NN+i)*3 + c] - coords[(b*NN+j)*3 + c];
        g_edges[((size_t)(b*NN+i)*NN + j)*3 + c] = d;
    }
    for (int e = 0; e < EB; e++) {
        int i = bonds[2*e], j = bonds[2*e+1];
        float d = coords[(b*NN+i)*3 + c] - coords[(b*NN+j)*3 + c];
        g_edges[((size_t)(b*NN+j)*NN + i)*3 + c] = -d;
    }
}

// ---------------- layer kernel A: LN1 + Q/KV projections + qWe ---------------
__global__ void __launch_bounds__(256) k_ln_proj(
    const float* __restrict__ ln_g, const float* __restrict__ ln_b,
    const float* __restrict__ Wq,  const float* __restrict__ bq,
    const float* __restrict__ Wkv, const float* __restrict__ bkv,
    const float* __restrict__ We,  const float* __restrict__ be)
{
    int row = blockIdx.x, tid = threadIdx.x;
    __shared__ float s_xn[DIMF];
    __shared__ float s_q[INNERD];
    __shared__ float sred[8];

    float xv = (tid < DIMF) ? g_nodes[row*DIMF + tid] : 0.f;
    float mean = blk_sum256(xv, sred) * (1.f/DIMF);
    float dv = (tid < DIMF) ? (xv - mean) : 0.f;
    float var = blk_sum256(dv*dv, sred) * (1.f/DIMF);
    if (tid < DIMF)
        s_xn[tid] = dv * rsqrtf(var + 1e-5f) * ln_g[tid] + ln_b[tid];
    __syncthreads();

    for (int o = tid; o < INNERD; o += 256) {
        float acc = bq[o];
        #pragma unroll 8
        for (int d = 0; d < DIMF; d++) acc = fmaf(s_xn[d], Wq[d*INNERD + o], acc);
        s_q[o] = acc;
        g_q[(size_t)row*INNERD + o] = acc;
    }
    for (int o = tid; o < 2*INNERD; o += 256) {
        float acc = bkv[o];
        #pragma unroll 8
        for (int d = 0; d < DIMF; d++) acc = fmaf(s_xn[d], Wkv[d*2*INNERD + o], acc);
        if (o < INNERD) g_kbe[(size_t)row*INNERD + o]          = acc + be[o];
        else            g_vbe[(size_t)row*INNERD + (o-INNERD)] = acc + be[o-INNERD];
    }
    __syncthreads();
    if (tid < NHEADS*3) {
        int h = tid / 3, c = tid % 3;
        float acc = 0.f;
        #pragma unroll 8
        for (int d = 0; d < DH; d++)
            acc = fmaf(s_q[h*DH + d], We[c*INNERD + h*DH + d], acc);
        g_qWe[row*NHEADS*3 + tid] = acc;
    }
}

// ---------------- layer kernel B: attention (warp = head) --------------------
__global__ void __launch_bounds__(256) k_attn(const float* __restrict__ We)
{
    int row = blockIdx.x, tid = threadIdx.x;
    int b = row / NN;
    __shared__ float s_q[INNERD];
    __shared__ float s_qWe[NHEADS*3];
    __shared__ float s_e[NN*3];
    __shared__ float s_attn[NHEADS*NN];

    for (int t = tid; t < INNERD; t += 256) s_q[t] = g_q[(size_t)row*INNERD + t];
    for (int t = tid; t < NN*3;   t += 256) s_e[t] = g_edges[(size_t)row*NN*3 + t];
    if (tid < NHEADS*3) s_qWe[tid] = g_qWe[row*NHEADS*3 + tid];
    __syncthreads();

    int h = tid >> 5, lane = tid & 31;
    float ev[4];
    float m = -1e30f;
    #pragma unroll
    for (int t = 0; t < 4; t++) {
        int j = lane + 32*t;
        const float* kb = g_kbe + (size_t)(b*NN + j)*INNERD + h*DH;
        float acc = 0.f;
        #pragma unroll 8
        for (int d = 0; d < DH; d++) acc = fmaf(s_q[h*DH + d], kb[d], acc);
        acc += s_e[j*3+0]*s_qWe[h*3+0] + s_e[j*3+1]*s_qWe[h*3+1] + s_e[j*3+2]*s_qWe[h*3+2];
        ev[t] = acc * SCALE;
        m = fmaxf(m, ev[t]);
    }
    #pragma unroll
    for (int off = 16; off > 0; off >>= 1)
        m = fmaxf(m, __shfl_xor_sync(0xffffffffu, m, off));
    float sum = 0.f;
    #pragma unroll
    for (int t = 0; t < 4; t++) { ev[t] = expf(ev[t] - m); sum += ev[t]; }
    #pragma unroll
    for (int off = 16; off > 0; off >>= 1)
        sum += __shfl_xor_sync(0xffffffffu, sum, off);
    float inv = 1.f / sum;

    float sc0 = 0.f, sc1 = 0.f, sc2 = 0.f;
    #pragma unroll
    for (int t = 0; t < 4; t++) {
        int j = lane + 32*t;
        float a = ev[t] * inv;
        s_attn[h*NN + j] = a;
        sc0 += a * s_e[j*3+0];
        sc1 += a * s_e[j*3+1];
        sc2 += a * s_e[j*3+2];
    }
    #pragma unroll
    for (int off = 16; off > 0; off >>= 1) {
        sc0 += __shfl_xor_sync(0xffffffffu, sc0, off);
        sc1 += __shfl_xor_sync(0xffffffffu, sc1, off);
        sc2 += __shfl_xor_sync(0xffffffffu, sc2, off);
    }
    __syncwarp();

    #pragma unroll
    for (int t2 = 0; t2 < 2; t2++) {
        int d = lane + 32*t2;
        float acc = 0.f;
        #pragma unroll 4
        for (int j = 0; j < NN; j++)
            acc = fmaf(s_attn[h*NN + j], g_vbe[(size_t)(b*NN + j)*INNERD + h*DH + d], acc);
        acc += sc0 * We[0*INNERD + h*DH + d]
             + sc1 * We[1*INNERD + h*DH + d]
             + sc2 * We[2*INNERD + h*DH + d];
        g_ao[(size_t)row*INNERD + h*DH + d] = acc;
    }
}

// ---------------- layer kernel C: Wo + gate1 + LN2 + FF + gate2 --------------
__global__ void __launch_bounds__(256) k_out_ff(
    const float* __restrict__ Wo,  const float* __restrict__ bo,
    const float* __restrict__ Wg1,
    const float* __restrict__ ln2g, const float* __restrict__ ln2b,
    const float* __restrict__ W1,  const float* __restrict__ b1,
    const float* __restrict__ W2,  const float* __restrict__ b2,
    const float* __restrict__ Wg2)
{
    int row = blockIdx.x, tid = threadIdx.x;
    __shared__ float s_ao[INNERD];
    __shared__ float s_res[DIMF];
    __shared__ float s_x[DIMF];
    __shared__ float s_h1[INNERD];
    __shared__ float sred[8];

    for (int t = tid; t < INNERD; t += 256) s_ao[t] = g_ao[(size_t)row*INNERD + t];
    if (tid < DIMF) s_res[tid] = g_nodes[row*DIMF + tid];
    __syncthreads();

    // x = ao @ Wo + bo
    if (tid < DIMF) {
        float acc = bo[tid];
        #pragma unroll 8
        for (int k = 0; k < INNERD; k++) acc = fmaf(s_ao[k], Wo[k*DIMF + tid], acc);
        s_x[tid] = acc;
    }
    __syncthreads();

    // gate1 (scalar per row)
    float p = 0.f;
    if (tid < DIMF) {
        float x = s_x[tid], r = s_res[tid];
        p = x * Wg1[tid] + r * Wg1[DIMF + tid] + (x - r) * Wg1[2*DIMF + tid];
    }
    float gs = blk_sum256(p, sred);
    float g1 = 1.f / (1.f + expf(-gs));
    float n1 = (tid < DIMF) ? (s_x[tid]*g1 + s_res[tid]*(1.f - g1)) : 0.f;
    __syncthreads();
    if (tid < DIMF) s_res[tid] = n1;     // new residual

    // LN2 over n1
    float mean = blk_sum256(n1, sred) * (1.f/DIMF);
    float dv = (tid < DIMF) ? (n1 - mean) : 0.f;
    float var = blk_sum256(dv*dv, sred) * (1.f/DIMF);
    if (tid < DIMF) s_x[tid] = dv * rsqrtf(var + 1e-5f) * ln2g[tid] + ln2b[tid];
    __syncthreads();

    // h1 = gelu_exact(xn @ W1 + b1)
    for (int o = tid; o < INNERD; o += 256) {
        float acc = b1[o];
        #pragma unroll 8
        for (int d = 0; d < DIMF; d++) acc = fmaf(s_x[d], W1[d*INNERD + o], acc);
        s_h1[o] = 0.5f * acc * (1.f + erff(acc * 0.70710678118654752f));
    }
    __syncthreads();

    // ff = h1 @ W2 + b2
    float ff = 0.f;
    if (tid < DIMF) {
        float acc = b2[tid];
        #pragma unroll 8
        for (int k = 0; k < INNERD; k++) acc = fmaf(s_h1[k], W2[k*DIMF + tid], acc);
        ff = acc;
    }
    // gate2
    float p2 = 0.f;
    if (tid < DIMF) {
        float r = s_res[tid];
        p2 = ff * Wg2[tid] + r * Wg2[DIMF + tid] + (ff - r) * Wg2[2*DIMF + tid];
    }
    float gs2 = blk_sum256(p2, sred);
    float g2 = 1.f / (1.f + expf(-gs2));
    if (tid < DIMF)
        g_nodes[row*DIMF + tid] = ff*g2 + s_res[tid]*(1.f - g2);
}

// ---------------- epilogue ----------------------------------------------------
__global__ void __launch_bounds__(256) k_final(const float* __restrict__ Wlin,
                                               const float* __restrict__ blin,
                                               float* __restrict__ out)
{
    __shared__ float sred[8];
    int tid = threadIdx.x;
    float acc = 0.f;
    for (int r = tid; r < BB*NN; r += 256) {
        float d = 0.f;
        #pragma unroll 8
        for (int f = 0; f < DIMF; f++) d = fmaf(g_nodes[r*DIMF + f], Wlin[f], d);
        acc += d;
    }
    float tot = blk_sum256(acc, sred);
    if (tid == 0) out[0] = tot + (float)(BB*NN) * blin[0];
}

// ---------------- launch -------------------------------------------------------
extern "C" void kernel_launch(void* const* d_in, const int* in_sizes, int n_in,
                              void* d_out, int out_size)
{
    const int*   indices  = (const int*)  d_in[0];
    const float* coords   = (const float*)d_in[1];
    const int*   bonds    = (const int*)  d_in[2];
    const float* noise    = (const float*)d_in[3];
    const float* atom_emb = (const float*)d_in[4];
    const float* ln1_g    = (const float*)d_in[5];
    const float* ln1_b    = (const float*)d_in[6];
    const float* Wq       = (const float*)d_in[7];
    const float* bq       = (const float*)d_in[8];
    const float* Wkv      = (const float*)d_in[9];
    const float* bkv      = (const float*)d_in[10];
    const float* We       = (const float*)d_in[11];
    const float* be       = (const float*)d_in[12];
    const float* Wo       = (const float*)d_in[13];
    const float* bo       = (const float*)d_in[14];
    const float* Wg1      = (const float*)d_in[15];
    const float* ln2g     = (const float*)d_in[16];
    const float* ln2b     = (const float*)d_in[17];
    const float* W1       = (const float*)d_in[18];
    const float* b1       = (const float*)d_in[19];
    const float* W2       = (const float*)d_in[20];
    const float* b2       = (const float*)d_in[21];
    const float* Wg2      = (const float*)d_in[22];
    const float* Wlin     = (const float*)d_in[23];
    const float* blin     = (const float*)d_in[24];

    k_init<<<128, 256>>>(indices, atom_emb, noise);
    k_edges<<<1, 32>>>(bonds, coords);

    for (int l = 0; l < DEPTHL; l++) {
        k_ln_proj<<<BB*NN, 256>>>(
            ln1_g + l*DIMF, ln1_b + l*DIMF,
            Wq  + (size_t)l*DIMF*INNERD,   bq  + (size_t)l*INNERD,
            Wkv + (size_t)l*DIMF*2*INNERD, bkv + (size_t)l*2*INNERD,
            We  + (size_t)l*3*INNERD,      be  + (size_t)l*INNERD);
        k_attn<<<BB*NN, 256>>>(We + (size_t)l*3*INNERD);
        k_out_ff<<<BB*NN, 256>>>(
            Wo + (size_t)l*INNERD*DIMF, bo + (size_t)l*DIMF,
            Wg1 + (size_t)l*3*DIMF,
            ln2g + (size_t)l*DIMF, ln2b + (size_t)l*DIMF,
            W1 + (size_t)l*DIMF*4*DIMF, b1 + (size_t)l*4*DIMF,
            W2 + (size_t)l*4*DIMF*DIMF, b2 + (size_t)l*DIMF,
            Wg2 + (size_t)l*3*DIMF);
    }

    k_final<<<1, 256>>>(Wlin, blin, (float*)d_out);
}

// round 2
// speedup vs baseline: 3.2395x; 3.2395x over previous
#include <cuda_runtime.h>
#include <math.h>

#define BB     2
#define NN     128
#define EB     160
#define DEPTHL 6
#define NHEADS 8
#define DH     64
#define INNERD 512
#define DIMF   128
#define NF     127
#define SCALE  0.125f  /* 64^-0.5 */

// ---------------- scratch (static device globals; no allocation) -------------
__device__ float g_nodes[BB*NN*DIMF];
__device__ float g_edges[BB*NN*NN*3];
__device__ float g_q   [BB*NN*INNERD];
__device__ float g_kbe [BB*NN*INNERD];
__device__ float g_vbe [BB*NN*INNERD];
__device__ float g_ao  [BB*NN*INNERD];

// ---------------- helpers ----------------------------------------------------
__device__ __forceinline__ float warp_sum(float v) {
    #pragma unroll
    for (int off = 16; off > 0; off >>= 1)
        v += __shfl_xor_sync(0xffffffffu, v, off);
    return v;
}
__device__ __forceinline__ float warp_max(float v) {
    #pragma unroll
    for (int off = 16; off > 0; off >>= 1)
        v = fmaxf(v, __shfl_xor_sync(0xffffffffu, v, off));
    return v;
}

// ---------------- prologue ----------------------------------------------------
__global__ void k_init(const int* __restrict__ indices,
                       const float* __restrict__ atom_emb,
                       const float* __restrict__ noise)
{
    int idx = blockIdx.x * blockDim.x + threadIdx.x;
    int stride = gridDim.x * blockDim.x;
    for (int t = idx; t < BB*NN*DIMF; t += stride) {
        int f  = t % DIMF;
        int bn = t / DIMF;
        g_nodes[t] = (f < NF) ? atom_emb[indices[bn] * NF + f] : noise[0];
    }
    for (int t = idx; t < BB*NN*NN*3; t += stride) g_edges[t] = 0.f;
}

// Sequential scatter matching JAX .at[].set ordering (phase1 fully, then phase2),
// parallel only over (b,c) which never collide.
__global__ void k_edges(const int* __restrict__ bonds,
                        const float* __restrict__ coords)
{
    int lane = threadIdx.x;
    if (blockIdx.x != 0 || lane >= BB*3) return;
    int b = lane / 3, c = lane % 3;
    for (int e = 0; e < EB; e++) {
        int i = bonds[2*e], j = bonds[2*e+1];
        float d = coords[(b*NN+i)*3 + c] - coords[(b*NN+j)*3 + c];
        g_edges[((size_t)(b*NN+i)*NN + j)*3 + c] = d;
    }
    for (int e = 0; e < EB; e++) {
        int i = bonds[2*e], j = bonds[2*e+1];
        float d = coords[(b*NN+i)*3 + c] - coords[(b*NN+j)*3 + c];
        g_edges[((size_t)(b*NN+j)*NN + i)*3 + c] = -d;
    }
}

// ---------------- layer kernel A: LN1 + Q/KV projections ---------------------
// grid = 16 row-tiles x 6 col-tiles = 96 blocks of 256.
// LN output stored transposed s_xnT[d][16] (stride 20) so compute reads float4.
#define RT_ROWS 16
#define XNT_STRIDE 20
__global__ void __launch_bounds__(256) k_ln_proj(
    const float* __restrict__ ln_g, const float* __restrict__ ln_b,
    const float* __restrict__ Wq,  const float* __restrict__ bq,
    const float* __restrict__ Wkv, const float* __restrict__ bkv,
    const float* __restrict__ be)
{
    __shared__ __align__(16) float s_xnT[DIMF * XNT_STRIDE];

    int rowTile = blockIdx.x / 6;
    int ct      = blockIdx.x % 6;
    int r0      = rowTile * RT_ROWS;
    int tid  = threadIdx.x;
    int wid  = tid >> 5, lane = tid & 31;

    // --- LayerNorm of 16 rows: warp wid handles rows 2*wid, 2*wid+1 ----------
    #pragma unroll
    for (int rr = 0; rr < 2; rr++) {
        int r = 2*wid + rr;
        int grow = r0 + r;
        float4 xv = *(const float4*)&g_nodes[grow*DIMF + lane*4];
        float s = xv.x + xv.y + xv.z + xv.w;
        float mean = warp_sum(s) * (1.f/DIMF);
        float dx = xv.x-mean, dy = xv.y-mean, dz = xv.z-mean, dw = xv.w-mean;
        float v = dx*dx + dy*dy + dz*dz + dw*dw;
        float rstd = rsqrtf(warp_sum(v) * (1.f/DIMF) + 1e-5f);
        #pragma unroll
        for (int q = 0; q < 4; q++) {
            int d = lane*4 + q;
            float val = (q==0?dx:q==1?dy:q==2?dz:dw);
            s_xnT[d*XNT_STRIDE + r] = val * rstd * __ldg(&ln_g[d]) + __ldg(&ln_b[d]);
        }
    }
    __syncthreads();

    // --- projection: this block's 256 output columns -------------------------
    int o = ct*256 + tid;          // 0..1535 : [0,512)=q, [512,1536)=kv
    const float* Wcol;
    int stride;
    if (o < 512) { Wcol = Wq + o; stride = INNERD; }
    else         { Wcol = Wkv + (o - 512); stride = 2*INNERD; }

    float acc[16];
    #pragma unroll
    for (int r = 0; r < 16; r++) acc[r] = 0.f;

    #pragma unroll 4
    for (int d = 0; d < DIMF; d++) {
        float w = __ldg(&Wcol[(size_t)d * stride]);
        float4 a0 = *(const float4*)&s_xnT[d*XNT_STRIDE + 0];
        float4 a1 = *(const float4*)&s_xnT[d*XNT_STRIDE + 4];
        float4 a2 = *(const float4*)&s_xnT[d*XNT_STRIDE + 8];
        float4 a3 = *(const float4*)&s_xnT[d*XNT_STRIDE + 12];
        acc[0]  = fmaf(a0.x, w, acc[0]);  acc[1]  = fmaf(a0.y, w, acc[1]);
        acc[2]  = fmaf(a0.z, w, acc[2]);  acc[3]  = fmaf(a0.w, w, acc[3]);
        acc[4]  = fmaf(a1.x, w, acc[4]);  acc[5]  = fmaf(a1.y, w, acc[5]);
        acc[6]  = fmaf(a1.z, w, acc[6]);  acc[7]  = fmaf(a1.w, w, acc[7]);
        acc[8]  = fmaf(a2.x, w, acc[8]);  acc[9]  = fmaf(a2.y, w, acc[9]);
        acc[10] = fmaf(a2.z, w, acc[10]); acc[11] = fmaf(a2.w, w, acc[11]);
        acc[12] = fmaf(a3.x, w, acc[12]); acc[13] = fmaf(a3.y, w, acc[13]);
        acc[14] = fmaf(a3.z, w, acc[14]); acc[15] = fmaf(a3.w, w, acc[15]);
    }

    if (o < 512) {
        float bias = __ldg(&bq[o]);
        #pragma unroll
        for (int r = 0; r < 16; r++)
            g_q[(size_t)(r0+r)*INNERD + o] = acc[r] + bias;
    } else {
        int ck = o - 512;
        float bias = __ldg(&bkv[ck]);
        if (ck < 512) {
            float bev = __ldg(&be[ck]);
            #pragma unroll
            for (int r = 0; r < 16; r++)
                g_kbe[(size_t)(r0+r)*INNERD + ck] = acc[r] + bias + bev;
        } else {
            int cv = ck - 512;
            float bev = __ldg(&be[cv]);
            #pragma unroll
            for (int r = 0; r < 16; r++)
                g_vbe[(size_t)(r0+r)*INNERD + cv] = acc[r] + bias + bev;
        }
    }
}

// ---------------- layer kernel B: attention ----------------------------------
// block = (b, h, i-tile of 16). K/V staged into padded smem, coalesced.
#define ITILE 16
#define KVPAD 65
// smem floats: k 128*65 + v 128*65 + q 16*64 + p 16*128 + qwe 48 + sc 48
#define ATTN_SMEM_FLOATS (128*KVPAD*2 + ITILE*DH + ITILE*NN + ITILE*3*2)
__global__ void __launch_bounds__(256) k_attn(const float* __restrict__ We)
{
    extern __shared__ __align__(16) float sm[];
    float* s_k   = sm;
    float* s_v   = s_k + 128*KVPAD;
    float* s_q   = s_v + 128*KVPAD;
    float* s_p   = s_q + ITILE*DH;
    float* s_qwe = s_p + ITILE*NN;
    float* s_sc  = s_qwe + ITILE*3;

    int bid = blockIdx.x;
    int b  = bid >> 6;
    int h  = (bid >> 3) & 7;
    int it = bid & 7;
    int tid = threadIdx.x, wid = tid >> 5, lane = tid & 31;

    // stage K,V (coalesced: d fast)
    for (int idx = tid; idx < 128*DH; idx += 256) {
        int j = idx >> 6, d = idx & 63;
        size_t goff = (size_t)(b*NN + j)*INNERD + h*DH + d;
        s_k[j*KVPAD + d] = g_kbe[goff];
        s_v[j*KVPAD + d] = g_vbe[goff];
    }
    for (int idx = tid; idx < ITILE*DH; idx += 256) {
        int il = idx >> 6, d = idx & 63;
        s_q[idx] = g_q[(size_t)(b*NN + it*ITILE + il)*INNERD + h*DH + d];
    }
    __syncthreads();

    // qWe[il][c] = sum_d q * We[c, h*64+d]
    if (tid < ITILE*3) {
        int il = tid / 3, c = tid % 3;
        float a = 0.f;
        #pragma unroll 8
        for (int d = 0; d < DH; d++)
            a = fmaf(s_q[il*DH + d], __ldg(&We[c*INNERD + h*DH + d]), a);
        s_qwe[tid] = a;
    }
    __syncthreads();

    // warp wid handles local rows i0, i0+1
    int i0  = wid * 2;
    int gi0 = it*ITILE + i0;     // i within batch

    float acc[2][4];
    #pragma unroll
    for (int ii = 0; ii < 2; ii++)
        #pragma unroll
        for (int jt = 0; jt < 4; jt++) acc[ii][jt] = 0.f;

    // q·k  (register-tiled q, 4 FMA per k LDS)
    for (int dt = 0; dt < DH; dt += 8) {
        float qr0[8], qr1[8];
        #pragma unroll
        for (int dd = 0; dd < 8; dd++) {
            qr0[dd] = s_q[ i0   *DH + dt + dd];
            qr1[dd] = s_q[(i0+1)*DH + dt + dd];
        }
        #pragma unroll
        for (int jt = 0; jt < 4; jt++) {
            const float* kp = &s_k[(lane + 32*jt)*KVPAD + dt];
            #pragma unroll
            for (int dd = 0; dd < 8; dd++) {
                float kv = kp[dd];
                acc[0][jt] = fmaf(qr0[dd], kv, acc[0][jt]);
                acc[1][jt] = fmaf(qr1[dd], kv, acc[1][jt]);
            }
        }
    }

    // edge term (kept in regs for the sc pass)
    float ev[2][4][3];
    float qw[2][3];
    #pragma unroll
    for (int ii = 0; ii < 2; ii++)
        #pragma unroll
        for (int c = 0; c < 3; c++) qw[ii][c] = s_qwe[(i0+ii)*3 + c];

    #pragma unroll
    for (int ii = 0; ii < 2; ii++) {
        int gi = gi0 + ii;
        #pragma unroll
        for (int jt = 0; jt < 4; jt++) {
            int j = lane + 32*jt;
            const float* ep = &g_edges[((size_t)(b*NN + gi)*NN + j)*3];
            float e0 = __ldg(&ep[0]), e1 = __ldg(&ep[1]), e2 = __ldg(&ep[2]);
            ev[ii][jt][0] = e0; ev[ii][jt][1] = e1; ev[ii][jt][2] = e2;
            float s = acc[ii][jt] + e0*qw[ii][0] + e1*qw[ii][1] + e2*qw[ii][2];
            acc[ii][jt] = s * SCALE;
        }
    }

    // softmax + prob store + sc = sum_j p*e
    #pragma unroll
    for (int ii = 0; ii < 2; ii++) {
        float m = fmaxf(fmaxf(acc[ii][0], acc[ii][1]), fmaxf(acc[ii][2], acc[ii][3]));
        m = warp_max(m);
        float sum = 0.f, p[4];
        #pragma unroll
        for (int jt = 0; jt < 4; jt++) { p[jt] = expf(acc[ii][jt] - m); sum += p[jt]; }
        sum = warp_sum(sum);
        float inv = 1.f / sum;
        float sc0 = 0.f, sc1 = 0.f, sc2 = 0.f;
        #pragma unroll
        for (int jt = 0; jt < 4; jt++) {
            int j = lane + 32*jt;
            float pv = p[jt] * inv;
            s_p[(i0+ii)*NN + j] = pv;
            sc0 = fmaf(pv, ev[ii][jt][0], sc0);
            sc1 = fmaf(pv, ev[ii][jt][1], sc1);
            sc2 = fmaf(pv, ev[ii][jt][2], sc2);
        }
        sc0 = warp_sum(sc0); sc1 = warp_sum(sc1); sc2 = warp_sum(sc2);
        if (lane == 0) {
            s_sc[(i0+ii)*3 + 0] = sc0;
            s_sc[(i0+ii)*3 + 1] = sc1;
            s_sc[(i0+ii)*3 + 2] = sc2;
        }
    }
    __syncwarp();   // s_p / s_sc of this warp's rows are warp-private

    // out = p @ v  (+ sc·We)
    int d0 = lane, d1 = lane + 32;
    float o00 = 0.f, o01 = 0.f, o10 = 0.f, o11 = 0.f;
    #pragma unroll 4
    for (int j = 0; j < NN; j++) {
        float p0 = s_p[ i0   *NN + j];
        float p1 = s_p[(i0+1)*NN + j];
        float v0 = s_v[j*KVPAD + d0];
        float v1 = s_v[j*KVPAD + d1];
        o00 = fmaf(p0, v0, o00); o01 = fmaf(p0, v1, o01);
        o10 = fmaf(p1, v0, o10); o11 = fmaf(p1, v1, o11);
    }
    #pragma unroll
    for (int c = 0; c < 3; c++) {
        float w0 = __ldg(&We[c*INNERD + h*DH + d0]);
        float w1 = __ldg(&We[c*INNERD + h*DH + d1]);
        o00 = fmaf(s_sc[ i0   *3 + c], w0, o00);
        o01 = fmaf(s_sc[ i0   *3 + c], w1, o01);
        o10 = fmaf(s_sc[(i0+1)*3 + c], w0, o10);
        o11 = fmaf(s_sc[(i0+1)*3 + c], w1, o11);
    }
    size_t base0 = (size_t)(b*NN + gi0    )*INNERD + h*DH;
    size_t base1 = (size_t)(b*NN + gi0 + 1)*INNERD + h*DH;
    g_ao[base0 + d0] = o00;  g_ao[base0 + d1] = o01;
    g_ao[base1 + d0] = o10;  g_ao[base1 + d1] = o11;
}

// ---------------- layer kernel C: Wo + gate1 + LN2 + FF + gate2 --------------
// block owns 4 rows end-to-end; transposed activations -> float4 per LDS.
__global__ void __launch_bounds__(256) k_out_ff(
    const float* __restrict__ Wo,  const float* __restrict__ bo,
    const float* __restrict__ Wg1,
    const float* __restrict__ ln2g, const float* __restrict__ ln2b,
    const float* __restrict__ W1,  const float* __restrict__ b1,
    const float* __restrict__ W2,  const float* __restrict__ b2,
    const float* __restrict__ Wg2)
{
    __shared__ __align__(16) float s_aoT[INNERD*4];   // [k][r]
    __shared__ __align__(16) float s_res[4*DIMF];     // [r][c]
    __shared__ __align__(16) float s_x  [4*DIMF];     // [r][c]
    __shared__ __align__(16) float s_xT [DIMF*4];     // [d][r]
    __shared__ __align__(16) float s_h1T[INNERD*4];   // [k][r]
    __shared__ __align__(16) float s_part[4*DIMF];    // split-k partials

    int tid = threadIdx.x, wid = tid >> 5, lane = tid & 31;
    int row0 = blockIdx.x * 4;

    // stage ao (transposed) and residual
    for (int idx = tid; idx < 4*INNERD; idx += 256) {
        int r = idx >> 9, k = idx & 511;
        s_aoT[k*4 + r] = g_ao[(size_t)(row0 + r)*INNERD + k];
    }
    for (int idx = tid; idx < 4*DIMF; idx += 256)
        s_res[idx] = g_nodes[(row0 + (idx >> 7))*DIMF + (idx & 127)];
    __syncthreads();

    // ---- x = ao @ Wo + bo (split-k over 2 groups) ---------------------------
    {
        int c = tid & 127, g = tid >> 7;
        float acc[4] = {0.f, 0.f, 0.f, 0.f};
        int k0 = g * 256;
        #pragma unroll 4
        for (int k = k0; k < k0 + 256; k++) {
            float4 a = *(const float4*)&s_aoT[k*4];
            float w = __ldg(&Wo[(size_t)k*DIMF + c]);
            acc[0] = fmaf(a.x, w, acc[0]); acc[1] = fmaf(a.y, w, acc[1]);
            acc[2] = fmaf(a.z, w, acc[2]); acc[3] = fmaf(a.w, w, acc[3]);
        }
        if (g == 1) {
            #pragma unroll
            for (int r = 0; r < 4; r++) s_part[r*DIMF + c] = acc[r];
        }
        __syncthreads();
        if (g == 0) {
            float bias = __ldg(&bo[c]);
            #pragma unroll
            for (int r = 0; r < 4; r++)
                s_x[r*DIMF + c] = acc[r] + s_part[r*DIMF + c] + bias;
        }
    }
    __syncthreads();

    // ---- gate1 + LN2 (warp per row) ----------------------------------------
    if (wid < 4) {
        int r = wid;
        float xv[4], rv[4], p = 0.f;
        #pragma unroll
        for (int q = 0; q < 4; q++) {
            int c = lane + 32*q;
            xv[q] = s_x[r*DIMF + c];
            rv[q] = s_res[r*DIMF + c];
            p += xv[q]*__ldg(&Wg1[c]) + rv[q]*__ldg(&Wg1[DIMF + c])
               + (xv[q]-rv[q])*__ldg(&Wg1[2*DIMF + c]);
        }
        float gs = warp_sum(p);
        float g1 = 1.f / (1.f + expf(-gs));
        float n1[4], msum = 0.f;
        #pragma unroll
        for (int q = 0; q < 4; q++) {
            n1[q] = xv[q]*g1 + rv[q]*(1.f - g1);
            msum += n1[q];
        }
        float mean = warp_sum(msum) * (1.f/DIMF);
        float vsum = 0.f;
        #pragma unroll
        for (int q = 0; q < 4; q++) { float d = n1[q]-mean; vsum += d*d; }
        float rstd = rsqrtf(warp_sum(vsum) * (1.f/DIMF) + 1e-5f);
        #pragma unroll
        for (int q = 0; q < 4; q++) {
            int c = lane + 32*q;
            s_res[r*DIMF + c] = n1[q];   // new residual
            s_xT[c*4 + r] = (n1[q]-mean)*rstd*__ldg(&ln2g[c]) + __ldg(&ln2b[c]);
        }
    }
    __syncthreads();

    // ---- h1 = gelu(xn @ W1 + b1) -------------------------------------------
    {
        int o = tid;            // and o+256
        float a0[4] = {0,0,0,0}, a1[4] = {0,0,0,0};
        #pragma unroll 4
        for (int d = 0; d < DIMF; d++) {
            float4 xv = *(const float4*)&s_xT[d*4];
            float w0 = __ldg(&W1[(size_t)d*INNERD + o]);
            float w1 = __ldg(&W1[(size_t)d*INNERD + o + 256]);
            a0[0] = fmaf(xv.x, w0, a0[0]); a0[1] = fmaf(xv.y, w0, a0[1]);
            a0[2] = fmaf(xv.z, w0, a0[2]); a0[3] = fmaf(xv.w, w0, a0[3]);
            a1[0] = fmaf(xv.x, w1, a1[0]); a1[1] = fmaf(xv.y, w1, a1[1]);
            a1[2] = fmaf(xv.z, w1, a1[2]); a1[3] = fmaf(xv.w, w1, a1[3]);
        }
        float b0v = __ldg(&b1[o]), b1v = __ldg(&b1[o + 256]);
        float4 h0, h1v;
        float u;
        u = a0[0]+b0v; h0.x  = 0.5f*u*(1.f+erff(u*0.70710678118654752f));
        u = a0[1]+b0v; h0.y  = 0.5f*u*(1.f+erff(u*0.70710678118654752f));
        u = a0[2]+b0v; h0.z  = 0.5f*u*(1.f+erff(u*0.70710678118654752f));
        u = a0[3]+b0v; h0.w  = 0.5f*u*(1.f+erff(u*0.70710678118654752f));
        u = a1[0]+b1v; h1v.x = 0.5f*u*(1.f+erff(u*0.70710678118654752f));
        u = a1[1]+b1v; h1v.y = 0.5f*u*(1.f+erff(u*0.70710678118654752f));
        u = a1[2]+b1v; h1v.z = 0.5f*u*(1.f+erff(u*0.70710678118654752f));
        u = a1[3]+b1v; h1v.w = 0.5f*u*(1.f+erff(u*0.70710678118654752f));
        *(float4*)&s_h1T[o*4]         = h0;
        *(float4*)&s_h1T[(o+256)*4]   = h1v;
    }
    __syncthreads();

    // ---- ff = h1 @ W2 + b2 (split-k over 2 groups) --------------------------
    {
        int c = tid & 127, g = tid >> 7;
        float acc[4] = {0.f, 0.f, 0.f, 0.f};
        int k0 = g * 256;
        #pragma unroll 4
        for (int k = k0; k < k0 + 256; k++) {
            float4 hh = *(const float4*)&s_h1T[k*4];
            float w = __ldg(&W2[(size_t)k*DIMF + c]);
            acc[0] = fmaf(hh.x, w, acc[0]); acc[1] = fmaf(hh.y, w, acc[1]);
            acc[2] = fmaf(hh.z, w, acc[2]); acc[3] = fmaf(hh.w, w, acc[3]);
        }
        if (g == 1) {
            #pragma unroll
            for (int r = 0; r < 4; r++) s_part[r*DIMF + c] = acc[r];
        }
        __syncthreads();
        if (g == 0) {
            float bias = __ldg(&b2[c]);
            #pragma unroll
            for (int r = 0; r < 4; r++)
                s_x[r*DIMF + c] = acc[r] + s_part[r*DIMF + c] + bias;
        }
    }
    __syncthreads();

    // ---- gate2 + write back -------------------------------------------------
    if (wid < 4) {
        int r = wid;
        float fv[4], rv[4], p = 0.f;
        #pragma unroll
        for (int q = 0; q < 4; q++) {
            int c = lane + 32*q;
            fv[q] = s_x[r*DIMF + c];
            rv[q] = s_res[r*DIMF + c];
            p += fv[q]*__ldg(&Wg2[c]) + rv[q]*__ldg(&Wg2[DIMF + c])
               + (fv[q]-rv[q])*__ldg(&Wg2[2*DIMF + c]);
        }
        float gs = warp_sum(p);
        float g2 = 1.f / (1.f + expf(-gs));
        #pragma unroll
        for (int q = 0; q < 4; q++) {
            int c = lane + 32*q;
            g_nodes[(row0 + r)*DIMF + c] = fv[q]*g2 + rv[q]*(1.f - g2);
        }
    }
}

// ---------------- epilogue ----------------------------------------------------
__global__ void __launch_bounds__(256) k_final(const float* __restrict__ Wlin,
                                               const float* __restrict__ blin,
                                               float* __restrict__ out)
{
    __shared__ float sred[8];
    int tid = threadIdx.x, wid = tid >> 5;
    float acc = 0.f;
    for (int r = tid >> 5; r < BB*NN; r += 8) {      // warp per row
        int lane = tid & 31;
        float4 x = *(const float4*)&g_nodes[r*DIMF + lane*4];
        float4 w = *(const float4*)&Wlin[lane*4];
        acc += x.x*w.x + x.y*w.y + x.z*w.z + x.w*w.w;
    }
    acc = warp_sum(acc);
    if ((tid & 31) == 0) sred[wid] = acc;
    __syncthreads();
    if (tid == 0) {
        float t = 0.f;
        #pragma unroll
        for (int w = 0; w < 8; w++) t += sred[w];
        out[0] = t + (float)(BB*NN) * blin[0];
    }
}

// ---------------- launch -------------------------------------------------------
extern "C" void kernel_launch(void* const* d_in, const int* in_sizes, int n_in,
                              void* d_out, int out_size)
{
    const int*   indices  = (const int*)  d_in[0];
    const float* coords   = (const float*)d_in[1];
    const int*   bonds    = (const int*)  d_in[2];
    const float* noise    = (const float*)d_in[3];
    const float* atom_emb = (const float*)d_in[4];
    const float* ln1_g    = (const float*)d_in[5];
    const float* ln1_b    = (const float*)d_in[6];
    const float* Wq       = (const float*)d_in[7];
    const float* bq       = (const float*)d_in[8];
    const float* Wkv      = (const float*)d_in[9];
    const float* bkv      = (const float*)d_in[10];
    const float* We       = (const float*)d_in[11];
    const float* be       = (const float*)d_in[12];
    const float* Wo       = (const float*)d_in[13];
    const float* bo       = (const float*)d_in[14];
    const float* Wg1      = (const float*)d_in[15];
    const float* ln2g     = (const float*)d_in[16];
    const float* ln2b     = (const float*)d_in[17];
    const float* W1       = (const float*)d_in[18];
    const float* b1       = (const float*)d_in[19];
    const float* W2       = (const float*)d_in[20];
    const float* b2       = (const float*)d_in[21];
    const float* Wg2      = (const float*)d_in[22];
    const float* Wlin     = (const float*)d_in[23];
    const float* blin     = (const float*)d_in[24];

    cudaFuncSetAttribute(k_attn, cudaFuncAttributeMaxDynamicSharedMemorySize,
                         ATTN_SMEM_FLOATS * (int)sizeof(float));

    k_init<<<128, 256>>>(indices, atom_emb, noise);
    k_edges<<<1, 32>>>(bonds, coords);

    for (int l = 0; l < DEPTHL; l++) {
        k_ln_proj<<<96, 256>>>(
            ln1_g + l*DIMF, ln1_b + l*DIMF,
            Wq  + (size_t)l*DIMF*INNERD,   bq  + (size_t)l*INNERD,
            Wkv + (size_t)l*DIMF*2*INNERD, bkv + (size_t)l*2*INNERD,
            be  + (size_t)l*INNERD);
        k_attn<<<128, 256, ATTN_SMEM_FLOATS * sizeof(float)>>>(
            We + (size_t)l*3*INNERD);
        k_out_ff<<<64, 256>>>(
            Wo + (size_t)l*INNERD*DIMF, bo + (size_t)l*DIMF,
            Wg1 + (size_t)l*3*DIMF,
            ln2g + (size_t)l*DIMF, ln2b + (size_t)l*DIMF,
            W1 + (size_t)l*DIMF*4*DIMF, b1 + (size_t)l*4*DIMF,
            W2 + (size_t)l*4*DIMF*DIMF, b2 + (size_t)l*DIMF,
            Wg2 + (size_t)l*3*DIMF);
    }

    k_final<<<1, 256>>>(Wlin, blin, (float*)d_out);
}

// round 3
// speedup vs baseline: 5.5398x; 1.7101x over previous
#include <cuda_runtime.h>
#include <math.h>

#define BB     2
#define NN     128
#define EB     160
#define DEPTHL 6
#define NHEADS 8
#define DH     64
#define INNERD 512
#define DIMF   128
#define NF     127
#define SCALE  0.125f  /* 64^-0.5 */

// ---------------- scratch (static device globals; no allocation) -------------
__device__ float g_nodes[BB*NN*DIMF];
__device__ float g_edges[BB*NN*NN*3];
__device__ float g_q   [BB*NN*INNERD];
__device__ float g_kbe [BB*NN*INNERD];
__device__ float g_vbe [BB*NN*INNERD];
__device__ float g_ao  [BB*NN*INNERD];

// ---------------- helpers ----------------------------------------------------
__device__ __forceinline__ float warp_sum(float v) {
    #pragma unroll
    for (int off = 16; off > 0; off >>= 1)
        v += __shfl_xor_sync(0xffffffffu, v, off);
    return v;
}
__device__ __forceinline__ float warp_max(float v) {
    #pragma unroll
    for (int off = 16; off > 0; off >>= 1)
        v = fmaxf(v, __shfl_xor_sync(0xffffffffu, v, off));
    return v;
}
__device__ __forceinline__ float gelu_exact(float u) {
    return 0.5f * u * (1.f + erff(u * 0.70710678118654752f));
}

// ---------------- prologue ----------------------------------------------------
__global__ void k_init(const int* __restrict__ indices,
                       const float* __restrict__ atom_emb,
                       const float* __restrict__ noise)
{
    int idx = blockIdx.x * blockDim.x + threadIdx.x;
    int stride = gridDim.x * blockDim.x;
    for (int t = idx; t < BB*NN*DIMF; t += stride) {
        int f  = t % DIMF;
        int bn = t / DIMF;
        g_nodes[t] = (f < NF) ? atom_emb[indices[bn] * NF + f] : noise[0];
    }
    for (int t = idx; t < BB*NN*NN*3; t += stride) g_edges[t] = 0.f;
}

// Parallel deterministic scatter equivalent to sequential:
//   phase1: for e: edges[:, i_e, j_e] = diff_e   (later e wins)
//   phase2: for e: edges[:, j_e, i_e] = -diff_e  (later e wins; beats phase1)
// Slot (j,i) final: -diff of LAST e with bond (i,j).
// Slot (i,j) final via phase1 only if no edge has bond (j,i).
__global__ void k_edges(const int* __restrict__ bonds,
                        const float* __restrict__ coords)
{
    __shared__ int sb[EB*2];
    int tid = threadIdx.x;
    for (int t = tid; t < EB*2; t += blockDim.x) sb[t] = bonds[t];
    __syncthreads();
    if (tid >= EB) return;
    int i = sb[2*tid], j = sb[2*tid+1];
    bool laterSame = false, revExists = false;
    #pragma unroll 4
    for (int e = 0; e < EB; e++) {
        int ie = sb[2*e], je = sb[2*e+1];
        if (e > tid && ie == i && je == j) laterSame = true;
        if (ie == j && je == i)            revExists = true;
    }
    bool w2 = !laterSame;                 // write at (j,i) = -diff
    bool w1 = !laterSame && !revExists;   // write at (i,j) = diff
    if (!w1 && !w2) return;
    for (int b = 0; b < BB; b++) {
        float d0 = coords[(b*NN+i)*3+0] - coords[(b*NN+j)*3+0];
        float d1 = coords[(b*NN+i)*3+1] - coords[(b*NN+j)*3+1];
        float d2 = coords[(b*NN+i)*3+2] - coords[(b*NN+j)*3+2];
        if (w2) {
            size_t o = ((size_t)(b*NN+j)*NN + i)*3;
            g_edges[o+0] = -d0; g_edges[o+1] = -d1; g_edges[o+2] = -d2;
        }
        if (w1) {
            size_t o = ((size_t)(b*NN+i)*NN + j)*3;
            g_edges[o+0] = d0; g_edges[o+1] = d1; g_edges[o+2] = d2;
        }
    }
}

// ---------------- layer kernel A: LN1 + Q/KV projections ---------------------
// grid = 16 row-tiles x 6 col-tiles(256 cols) = 96 blocks of 256 threads.
// thread = 4 cols (float4 weight LDG.128) x 4 rows. 16 FMA per LDG128.
#define RT_ROWS 16
#define XNT_STRIDE 20
__global__ void __launch_bounds__(256) k_ln_proj(
    const float* __restrict__ ln_g, const float* __restrict__ ln_b,
    const float* __restrict__ Wq,  const float* __restrict__ bq,
    const float* __restrict__ Wkv, const float* __restrict__ bkv,
    const float* __restrict__ be)
{
    __shared__ __align__(16) float s_xnT[DIMF * XNT_STRIDE];   // [d][row16]

    int rowTile = blockIdx.x / 6;
    int ct      = blockIdx.x % 6;
    int r0      = rowTile * RT_ROWS;
    int tid  = threadIdx.x;
    int wid  = tid >> 5, lane = tid & 31;

    // --- LayerNorm of 16 rows: warp wid handles rows 2*wid, 2*wid+1 ----------
    #pragma unroll
    for (int rr = 0; rr < 2; rr++) {
        int r = 2*wid + rr;
        int grow = r0 + r;
        float4 xv = *(const float4*)&g_nodes[grow*DIMF + lane*4];
        float s = xv.x + xv.y + xv.z + xv.w;
        float mean = warp_sum(s) * (1.f/DIMF);
        float dx = xv.x-mean, dy = xv.y-mean, dz = xv.z-mean, dw = xv.w-mean;
        float v = dx*dx + dy*dy + dz*dz + dw*dw;
        float rstd = rsqrtf(warp_sum(v) * (1.f/DIMF) + 1e-5f);
        #pragma unroll
        for (int q = 0; q < 4; q++) {
            int d = lane*4 + q;
            float val = (q==0?dx:q==1?dy:q==2?dz:dw);
            s_xnT[d*XNT_STRIDE + r] = val * rstd * __ldg(&ln_g[d]) + __ldg(&ln_b[d]);
        }
    }
    __syncthreads();

    // --- projection ----------------------------------------------------------
    int quad = tid & 63;            // 64 quads of 4 cols -> 256 cols
    int rg   = tid >> 6;            // 4 row-groups of 4 rows
    int col  = ct*256 + quad*4;     // 0..1535

    const float* Wp;
    int stride;
    int region;                     // 0=q, 1=k, 2=v
    int rcol;                       // column within region's output buffer
    if (col < 512)       { Wp = Wq  + col;          stride = INNERD;   region = 0; rcol = col; }
    else {
        int ck = col - 512;
        Wp = Wkv + ck; stride = 2*INNERD;
        if (ck < 512) { region = 1; rcol = ck; }
        else          { region = 2; rcol = ck - 512; }
    }

    float a00=0,a01=0,a02=0,a03=0, a10=0,a11=0,a12=0,a13=0;
    float a20=0,a21=0,a22=0,a23=0, a30=0,a31=0,a32=0,a33=0;

    #pragma unroll 4
    for (int d = 0; d < DIMF; d++) {
        float4 w4 = __ldg((const float4*)(Wp + (size_t)d*stride));
        float4 x4 = *(const float4*)&s_xnT[d*XNT_STRIDE + rg*4];
        a00=fmaf(x4.x,w4.x,a00); a01=fmaf(x4.x,w4.y,a01); a02=fmaf(x4.x,w4.z,a02); a03=fmaf(x4.x,w4.w,a03);
        a10=fmaf(x4.y,w4.x,a10); a11=fmaf(x4.y,w4.y,a11); a12=fmaf(x4.y,w4.z,a12); a13=fmaf(x4.y,w4.w,a13);
        a20=fmaf(x4.z,w4.x,a20); a21=fmaf(x4.z,w4.y,a21); a22=fmaf(x4.z,w4.z,a22); a23=fmaf(x4.z,w4.w,a23);
        a30=fmaf(x4.w,w4.x,a30); a31=fmaf(x4.w,w4.y,a31); a32=fmaf(x4.w,w4.z,a32); a33=fmaf(x4.w,w4.w,a33);
    }

    float4 bias;
    if (region == 0)      bias = __ldg((const float4*)(bq + rcol));
    else {
        float4 bk = __ldg((const float4*)(bkv + (region==1 ? rcol : rcol+512)));
        float4 bv = __ldg((const float4*)(be + rcol));
        bias = make_float4(bk.x+bv.x, bk.y+bv.y, bk.z+bv.z, bk.w+bv.w);
    }
    float* dst = (region==0) ? g_q : (region==1) ? g_kbe : g_vbe;
    int rowbase = r0 + rg*4;
    float4 o0 = make_float4(a00+bias.x, a01+bias.y, a02+bias.z, a03+bias.w);
    float4 o1 = make_float4(a10+bias.x, a11+bias.y, a12+bias.z, a13+bias.w);
    float4 o2 = make_float4(a20+bias.x, a21+bias.y, a22+bias.z, a23+bias.w);
    float4 o3 = make_float4(a30+bias.x, a31+bias.y, a32+bias.z, a33+bias.w);
    *(float4*)&dst[(size_t)(rowbase+0)*INNERD + rcol] = o0;
    *(float4*)&dst[(size_t)(rowbase+1)*INNERD + rcol] = o1;
    *(float4*)&dst[(size_t)(rowbase+2)*INNERD + rcol] = o2;
    *(float4*)&dst[(size_t)(rowbase+3)*INNERD + rcol] = o3;
}

// ---------------- layer kernel B: attention ----------------------------------
// block = (b, h, i-tile of 16); float4 K/V smem, stride 17 float4.
#define ITILE 16
#define KV4   17
#define ATTN_SMEM_FLOATS (2*NN*KV4*4 + ITILE*16*4 + ITILE*NN + ITILE*3*2)
__global__ void __launch_bounds__(256) k_attn(const float* __restrict__ We)
{
    extern __shared__ __align__(16) float sm[];
    float4* s_k4  = (float4*)sm;                       // [128][17]
    float4* s_v4  = s_k4 + NN*KV4;
    float4* s_q4  = s_v4 + NN*KV4;                     // [16][16]
    float*  s_p   = (float*)(s_q4 + ITILE*16);         // [16][128]
    float*  s_qwe = s_p + ITILE*NN;                    // [16][3]
    float*  s_sc  = s_qwe + ITILE*3;                   // [16][3]

    int bid = blockIdx.x;
    int b  = bid >> 6;
    int h  = (bid >> 3) & 7;
    int it = bid & 7;
    int tid = threadIdx.x, wid = tid >> 5, lane = tid & 31;

    // stage K,V as float4 (coalesced)
    for (int idx = tid; idx < NN*16; idx += 256) {
        int j = idx >> 4, d4 = idx & 15;
        size_t goff = ((size_t)(b*NN + j)*INNERD + h*DH) >> 2;
        s_k4[j*KV4 + d4] = ((const float4*)g_kbe)[goff + d4];
        s_v4[j*KV4 + d4] = ((const float4*)g_vbe)[goff + d4];
    }
    for (int idx = tid; idx < ITILE*16; idx += 256) {
        int il = idx >> 4, d4 = idx & 15;
        s_q4[il*16 + d4] =
            ((const float4*)g_q)[(((size_t)(b*NN + it*ITILE + il)*INNERD + h*DH) >> 2) + d4];
    }
    __syncthreads();

    // qWe[il][c]
    if (tid < ITILE*3) {
        int il = tid / 3, c = tid % 3;
        const float* qf = (const float*)&s_q4[il*16];
        float a = 0.f;
        #pragma unroll 8
        for (int d = 0; d < DH; d++)
            a = fmaf(qf[d], __ldg(&We[c*INNERD + h*DH + d]), a);
        s_qwe[tid] = a;
    }
    __syncthreads();

    int i0  = wid * 2;
    int gi0 = it*ITILE + i0;

    float acc[2][4] = {{0,0,0,0},{0,0,0,0}};

    // q·k with float4 smem
    #pragma unroll 4
    for (int d4 = 0; d4 < 16; d4++) {
        float4 q0 = s_q4[ i0   *16 + d4];
        float4 q1 = s_q4[(i0+1)*16 + d4];
        #pragma unroll
        for (int jt = 0; jt < 4; jt++) {
            float4 k4 = s_k4[(lane + 32*jt)*KV4 + d4];
            acc[0][jt] = fmaf(q0.x,k4.x,fmaf(q0.y,k4.y,fmaf(q0.z,k4.z,fmaf(q0.w,k4.w,acc[0][jt]))));
            acc[1][jt] = fmaf(q1.x,k4.x,fmaf(q1.y,k4.y,fmaf(q1.z,k4.z,fmaf(q1.w,k4.w,acc[1][jt]))));
        }
    }

    // edge term
    float ev[2][4][3];
    float qw[2][3];
    #pragma unroll
    for (int ii = 0; ii < 2; ii++)
        #pragma unroll
        for (int c = 0; c < 3; c++) qw[ii][c] = s_qwe[(i0+ii)*3 + c];

    #pragma unroll
    for (int ii = 0; ii < 2; ii++) {
        int gi = gi0 + ii;
        #pragma unroll
        for (int jt = 0; jt < 4; jt++) {
            int j = lane + 32*jt;
            const float* ep = &g_edges[((size_t)(b*NN + gi)*NN + j)*3];
            float e0 = __ldg(&ep[0]), e1 = __ldg(&ep[1]), e2 = __ldg(&ep[2]);
            ev[ii][jt][0] = e0; ev[ii][jt][1] = e1; ev[ii][jt][2] = e2;
            float s = acc[ii][jt] + e0*qw[ii][0] + e1*qw[ii][1] + e2*qw[ii][2];
            acc[ii][jt] = s * SCALE;
        }
    }

    // softmax + sc
    #pragma unroll
    for (int ii = 0; ii < 2; ii++) {
        float m = fmaxf(fmaxf(acc[ii][0], acc[ii][1]), fmaxf(acc[ii][2], acc[ii][3]));
        m = warp_max(m);
        float sum = 0.f, p[4];
        #pragma unroll
        for (int jt = 0; jt < 4; jt++) { p[jt] = expf(acc[ii][jt] - m); sum += p[jt]; }
        sum = warp_sum(sum);
        float inv = 1.f / sum;
        float sc0 = 0.f, sc1 = 0.f, sc2 = 0.f;
        #pragma unroll
        for (int jt = 0; jt < 4; jt++) {
            int j = lane + 32*jt;
            float pv = p[jt] * inv;
            s_p[(i0+ii)*NN + j] = pv;
            sc0 = fmaf(pv, ev[ii][jt][0], sc0);
            sc1 = fmaf(pv, ev[ii][jt][1], sc1);
            sc2 = fmaf(pv, ev[ii][jt][2], sc2);
        }
        sc0 = warp_sum(sc0); sc1 = warp_sum(sc1); sc2 = warp_sum(sc2);
        if (lane == 0) {
            s_sc[(i0+ii)*3 + 0] = sc0;
            s_sc[(i0+ii)*3 + 1] = sc1;
            s_sc[(i0+ii)*3 + 2] = sc2;
        }
    }
    __syncwarp();

    // out = p @ v : lane = (half, d4); j split across halves, shfl-reduce.
    int half = lane >> 4, d4 = lane & 15;
    float4 o0 = make_float4(0,0,0,0), o1 = make_float4(0,0,0,0);
    int j0 = half * 64;
    #pragma unroll 4
    for (int j = j0; j < j0 + 64; j++) {
        float4 v4 = s_v4[j*KV4 + d4];
        float p0 = s_p[ i0   *NN + j];
        float p1 = s_p[(i0+1)*NN + j];
        o0.x=fmaf(p0,v4.x,o0.x); o0.y=fmaf(p0,v4.y,o0.y); o0.z=fmaf(p0,v4.z,o0.z); o0.w=fmaf(p0,v4.w,o0.w);
        o1.x=fmaf(p1,v4.x,o1.x); o1.y=fmaf(p1,v4.y,o1.y); o1.z=fmaf(p1,v4.z,o1.z); o1.w=fmaf(p1,v4.w,o1.w);
    }
    o0.x += __shfl_xor_sync(0xffffffffu, o0.x, 16);
    o0.y += __shfl_xor_sync(0xffffffffu, o0.y, 16);
    o0.z += __shfl_xor_sync(0xffffffffu, o0.z, 16);
    o0.w += __shfl_xor_sync(0xffffffffu, o0.w, 16);
    o1.x += __shfl_xor_sync(0xffffffffu, o1.x, 16);
    o1.y += __shfl_xor_sync(0xffffffffu, o1.y, 16);
    o1.z += __shfl_xor_sync(0xffffffffu, o1.z, 16);
    o1.w += __shfl_xor_sync(0xffffffffu, o1.w, 16);

    if (half == 0) {
        #pragma unroll
        for (int c = 0; c < 3; c++) {
            float4 w4 = __ldg((const float4*)(We + c*INNERD + h*DH + d4*4));
            float s0 = s_sc[ i0   *3 + c], s1 = s_sc[(i0+1)*3 + c];
            o0.x=fmaf(s0,w4.x,o0.x); o0.y=fmaf(s0,w4.y,o0.y); o0.z=fmaf(s0,w4.z,o0.z); o0.w=fmaf(s0,w4.w,o0.w);
            o1.x=fmaf(s1,w4.x,o1.x); o1.y=fmaf(s1,w4.y,o1.y); o1.z=fmaf(s1,w4.z,o1.z); o1.w=fmaf(s1,w4.w,o1.w);
        }
        *(float4*)&g_ao[(size_t)(b*NN + gi0    )*INNERD + h*DH + d4*4] = o0;
        *(float4*)&g_ao[(size_t)(b*NN + gi0 + 1)*INNERD + h*DH + d4*4] = o1;
    }
}

// ---------------- layer kernel C: Wo + gate1 + LN2 + FF + gate2 --------------
// 512 threads, 4 rows/block (grid 64). Split-K warp groups + smem reduce.
__global__ void __launch_bounds__(512) k_out_ff(
    const float* __restrict__ Wo,  const float* __restrict__ bo,
    const float* __restrict__ Wg1,
    const float* __restrict__ ln2g, const float* __restrict__ ln2b,
    const float* __restrict__ W1,  const float* __restrict__ b1,
    const float* __restrict__ W2,  const float* __restrict__ b2,
    const float* __restrict__ Wg2)
{
    __shared__ __align__(16) float s_buf [2048];  // aoT then h1T: [k][r] float4
    __shared__ __align__(16) float s_red [8192];  // split-K partials
    __shared__ __align__(16) float s_lnT [512];   // [d][r] float4
    __shared__ __align__(16) float s_xcol[512];   // [c][r] float4
    __shared__ __align__(16) float s_res [512];   // [r][c]

    float4* s_buf4  = (float4*)s_buf;
    float4* s_red4  = (float4*)s_red;
    float4* s_lnT4  = (float4*)s_lnT;
    float4* s_xcol4 = (float4*)s_xcol;

    int tid = threadIdx.x, wid = tid >> 5, lane = tid & 31;
    int row0 = blockIdx.x * 4;

    // stage aoT [k][r] and residual [r][c]
    for (int idx = tid; idx < 4*INNERD; idx += 512) {
        int r = idx >> 9, k = idx & 511;
        s_buf[k*4 + r] = g_ao[(size_t)(row0 + r)*INNERD + k];
    }
    for (int idx = tid; idx < 4*DIMF; idx += 512)
        s_res[idx] = g_nodes[(row0 + (idx >> 7))*DIMF + (idx & 127)];
    __syncthreads();

    // ---- x = ao @ Wo + bo : 16 K-groups x 32 iters --------------------------
    {
        int c4 = tid & 31, kg = tid >> 5;
        float a[4][4] = {{0,0,0,0},{0,0,0,0},{0,0,0,0},{0,0,0,0}};
        int k0 = kg * 32;
        #pragma unroll 4
        for (int k = k0; k < k0 + 32; k++) {
            float4 w4 = __ldg((const float4*)(Wo + (size_t)k*DIMF + c4*4));
            float4 x4 = s_buf4[k];
            a[0][0]=fmaf(x4.x,w4.x,a[0][0]); a[0][1]=fmaf(x4.x,w4.y,a[0][1]); a[0][2]=fmaf(x4.x,w4.z,a[0][2]); a[0][3]=fmaf(x4.x,w4.w,a[0][3]);
            a[1][0]=fmaf(x4.y,w4.x,a[1][0]); a[1][1]=fmaf(x4.y,w4.y,a[1][1]); a[1][2]=fmaf(x4.y,w4.z,a[1][2]); a[1][3]=fmaf(x4.y,w4.w,a[1][3]);
            a[2][0]=fmaf(x4.z,w4.x,a[2][0]); a[2][1]=fmaf(x4.z,w4.y,a[2][1]); a[2][2]=fmaf(x4.z,w4.z,a[2][2]); a[2][3]=fmaf(x4.z,w4.w,a[2][3]);
            a[3][0]=fmaf(x4.w,w4.x,a[3][0]); a[3][1]=fmaf(x4.w,w4.y,a[3][1]); a[3][2]=fmaf(x4.w,w4.z,a[3][2]); a[3][3]=fmaf(x4.w,w4.w,a[3][3]);
        }
        #pragma unroll
        for (int cc = 0; cc < 4; cc++)
            s_red4[kg*DIMF + c4*4 + cc] = make_float4(a[0][cc], a[1][cc], a[2][cc], a[3][cc]);
    }
    __syncthreads();
    if (tid < DIMF) {
        float4 s = make_float4(0,0,0,0);
        #pragma unroll
        for (int kg = 0; kg < 16; kg++) {
            float4 p = s_red4[kg*DIMF + tid];
            s.x += p.x; s.y += p.y; s.z += p.z; s.w += p.w;
        }
        float bb = __ldg(&bo[tid]);
        s.x += bb; s.y += bb; s.z += bb; s.w += bb;
        s_xcol4[tid] = s;
    }
    __syncthreads();

    // ---- gate1 + LN2 (warp per row) -----------------------------------------
    if (wid < 4) {
        int r = wid;
        float xv[4], rv[4], p = 0.f;
        #pragma unroll
        for (int q = 0; q < 4; q++) {
            int c = lane + 32*q;
            xv[q] = s_xcol[c*4 + r];
            rv[q] = s_res[r*DIMF + c];
            p += xv[q]*__ldg(&Wg1[c]) + rv[q]*__ldg(&Wg1[DIMF + c])
               + (xv[q]-rv[q])*__ldg(&Wg1[2*DIMF + c]);
        }
        float gs = warp_sum(p);
        float g1 = 1.f / (1.f + expf(-gs));
        float n1[4], msum = 0.f;
        #pragma unroll
        for (int q = 0; q < 4; q++) {
            n1[q] = xv[q]*g1 + rv[q]*(1.f - g1);
            msum += n1[q];
        }
        float mean = warp_sum(msum) * (1.f/DIMF);
        float vsum = 0.f;
        #pragma unroll
        for (int q = 0; q < 4; q++) { float d = n1[q]-mean; vsum += d*d; }
        float rstd = rsqrtf(warp_sum(vsum) * (1.f/DIMF) + 1e-5f);
        #pragma unroll
        for (int q = 0; q < 4; q++) {
            int c = lane + 32*q;
            s_res[r*DIMF + c] = n1[q];
            s_lnT[c*4 + r] = (n1[q]-mean)*rstd*__ldg(&ln2g[c]) + __ldg(&ln2b[c]);
        }
    }
    __syncthreads();

    // ---- h1 = gelu(xn @ W1 + b1) : 4 K-groups x 32 iters --------------------
    {
        int c4 = tid & 127, kg = tid >> 7;
        float a[4][4] = {{0,0,0,0},{0,0,0,0},{0,0,0,0},{0,0,0,0}};
        int k0 = kg * 32;
        #pragma unroll 4
        for (int k = k0; k < k0 + 32; k++) {
            float4 w4 = __ldg((const float4*)(W1 + (size_t)k*INNERD + c4*4));
            float4 x4 = s_lnT4[k];
            a[0][0]=fmaf(x4.x,w4.x,a[0][0]); a[0][1]=fmaf(x4.x,w4.y,a[0][1]); a[0][2]=fmaf(x4.x,w4.z,a[0][2]); a[0][3]=fmaf(x4.x,w4.w,a[0][3]);
            a[1][0]=fmaf(x4.y,w4.x,a[1][0]); a[1][1]=fmaf(x4.y,w4.y,a[1][1]); a[1][2]=fmaf(x4.y,w4.z,a[1][2]); a[1][3]=fmaf(x4.y,w4.w,a[1][3]);
            a[2][0]=fmaf(x4.z,w4.x,a[2][0]); a[2][1]=fmaf(x4.z,w4.y,a[2][1]); a[2][2]=fmaf(x4.z,w4.z,a[2][2]); a[2][3]=fmaf(x4.z,w4.w,a[2][3]);
            a[3][0]=fmaf(x4.w,w4.x,a[3][0]); a[3][1]=fmaf(x4.w,w4.y,a[3][1]); a[3][2]=fmaf(x4.w,w4.z,a[3][2]); a[3][3]=fmaf(x4.w,w4.w,a[3][3]);
        }
        #pragma unroll
        for (int cc = 0; cc < 4; cc++)
            s_red4[kg*INNERD + c4*4 + cc] = make_float4(a[0][cc], a[1][cc], a[2][cc], a[3][cc]);
    }
    __syncthreads();
    {
        int col = tid;   // 512 cols
        float4 s = make_float4(0,0,0,0);
        #pragma unroll
        for (int kg = 0; kg < 4; kg++) {
            float4 p = s_red4[kg*INNERD + col];
            s.x += p.x; s.y += p.y; s.z += p.z; s.w += p.w;
        }
        float bb = __ldg(&b1[col]);
        s.x = gelu_exact(s.x + bb);
        s.y = gelu_exact(s.y + bb);
        s.z = gelu_exact(s.z + bb);
        s.w = gelu_exact(s.w + bb);
        s_buf4[col] = s;    // h1T [k][r]
    }
    __syncthreads();

    // ---- ff = h1 @ W2 + b2 : 16 K-groups x 32 iters -------------------------
    {
        int c4 = tid & 31, kg = tid >> 5;
        float a[4][4] = {{0,0,0,0},{0,0,0,0},{0,0,0,0},{0,0,0,0}};
        int k0 = kg * 32;
        #pragma unroll 4
        for (int k = k0; k < k0 + 32; k++) {
            float4 w4 = __ldg((const float4*)(W2 + (size_t)k*DIMF + c4*4));
            float4 x4 = s_buf4[k];
            a[0][0]=fmaf(x4.x,w4.x,a[0][0]); a[0][1]=fmaf(x4.x,w4.y,a[0][1]); a[0][2]=fmaf(x4.x,w4.z,a[0][2]); a[0][3]=fmaf(x4.x,w4.w,a[0][3]);
            a[1][0]=fmaf(x4.y,w4.x,a[1][0]); a[1][1]=fmaf(x4.y,w4.y,a[1][1]); a[1][2]=fmaf(x4.y,w4.z,a[1][2]); a[1][3]=fmaf(x4.y,w4.w,a[1][3]);
            a[2][0]=fmaf(x4.z,w4.x,a[2][0]); a[2][1]=fmaf(x4.z,w4.y,a[2][1]); a[2][2]=fmaf(x4.z,w4.z,a[2][2]); a[2][3]=fmaf(x4.z,w4.w,a[2][3]);
            a[3][0]=fmaf(x4.w,w4.x,a[3][0]); a[3][1]=fmaf(x4.w,w4.y,a[3][1]); a[3][2]=fmaf(x4.w,w4.z,a[3][2]); a[3][3]=fmaf(x4.w,w4.w,a[3][3]);
        }
        #pragma unroll
        for (int cc = 0; cc < 4; cc++)
            s_red4[kg*DIMF + c4*4 + cc] = make_float4(a[0][cc], a[1][cc], a[2][cc], a[3][cc]);
    }
    __syncthreads();
    if (tid < DIMF) {
        float4 s = make_float4(0,0,0,0);
        #pragma unroll
        for (int kg = 0; kg < 16; kg++) {
            float4 p = s_red4[kg*DIMF + tid];
            s.x += p.x; s.y += p.y; s.z += p.z; s.w += p.w;
        }
        float bb = __ldg(&b2[tid]);
        s.x += bb; s.y += bb; s.z += bb; s.w += bb;
        s_xcol4[tid] = s;
    }
    __syncthreads();

    // ---- gate2 + write back -------------------------------------------------
    if (wid < 4) {
        int r = wid;
        float fv[4], rv[4], p = 0.f;
        #pragma unroll
        for (int q = 0; q < 4; q++) {
            int c = lane + 32*q;
            fv[q] = s_xcol[c*4 + r];
            rv[q] = s_res[r*DIMF + c];
            p += fv[q]*__ldg(&Wg2[c]) + rv[q]*__ldg(&Wg2[DIMF + c])
               + (fv[q]-rv[q])*__ldg(&Wg2[2*DIMF + c]);
        }
        float gs = warp_sum(p);
        float g2 = 1.f / (1.f + expf(-gs));
        #pragma unroll
        for (int q = 0; q < 4; q++) {
            int c = lane + 32*q;
            g_nodes[(row0 + r)*DIMF + c] = fv[q]*g2 + rv[q]*(1.f - g2);
        }
    }
}

// ---------------- epilogue ----------------------------------------------------
__global__ void __launch_bounds__(512) k_final(const float* __restrict__ Wlin,
                                               const float* __restrict__ blin,
                                               float* __restrict__ out)
{
    __shared__ float sred[16];
    int tid = threadIdx.x, wid = tid >> 5, lane = tid & 31;
    float acc = 0.f;
    for (int r = wid; r < BB*NN; r += 16) {
        float4 x = *(const float4*)&g_nodes[r*DIMF + lane*4];
        float4 w = *(const float4*)&Wlin[lane*4];
        acc += x.x*w.x + x.y*w.y + x.z*w.z + x.w*w.w;
    }
    acc = warp_sum(acc);
    if (lane == 0) sred[wid] = acc;
    __syncthreads();
    if (tid == 0) {
        float t = 0.f;
        #pragma unroll
        for (int w = 0; w < 16; w++) t += sred[w];
        out[0] = t + (float)(BB*NN) * blin[0];
    }
}

// ---------------- launch -------------------------------------------------------
extern "C" void kernel_launch(void* const* d_in, const int* in_sizes, int n_in,
                              void* d_out, int out_size)
{
    const int*   indices  = (const int*)  d_in[0];
    const float* coords   = (const float*)d_in[1];
    const int*   bonds    = (const int*)  d_in[2];
    const float* noise    = (const float*)d_in[3];
    const float* atom_emb = (const float*)d_in[4];
    const float* ln1_g    = (const float*)d_in[5];
    const float* ln1_b    = (const float*)d_in[6];
    const float* Wq       = (const float*)d_in[7];
    const float* bq       = (const float*)d_in[8];
    const float* Wkv      = (const float*)d_in[9];
    const float* bkv      = (const float*)d_in[10];
    const float* We       = (const float*)d_in[11];
    const float* be       = (const float*)d_in[12];
    const float* Wo       = (const float*)d_in[13];
    const float* bo       = (const float*)d_in[14];
    const float* Wg1      = (const float*)d_in[15];
    const float* ln2g     = (const float*)d_in[16];
    const float* ln2b     = (const float*)d_in[17];
    const float* W1       = (const float*)d_in[18];
    const float* b1       = (const float*)d_in[19];
    const float* W2       = (const float*)d_in[20];
    const float* b2       = (const float*)d_in[21];
    const float* Wg2      = (const float*)d_in[22];
    const float* Wlin     = (const float*)d_in[23];
    const float* blin     = (const float*)d_in[24];

    cudaFuncSetAttribute(k_attn, cudaFuncAttributeMaxDynamicSharedMemorySize,
                         ATTN_SMEM_FLOATS * (int)sizeof(float));

    k_init<<<128, 256>>>(indices, atom_emb, noise);
    k_edges<<<1, 192>>>(bonds, coords);

    for (int l = 0; l < DEPTHL; l++) {
        k_ln_proj<<<96, 256>>>(
            ln1_g + l*DIMF, ln1_b + l*DIMF,
            Wq  + (size_t)l*DIMF*INNERD,   bq  + (size_t)l*INNERD,
            Wkv + (size_t)l*DIMF*2*INNERD, bkv + (size_t)l*2*INNERD,
            be  + (size_t)l*INNERD);
        k_attn<<<128, 256, ATTN_SMEM_FLOATS * sizeof(float)>>>(
            We + (size_t)l*3*INNERD);
        k_out_ff<<<64, 512>>>(
            Wo + (size_t)l*INNERD*DIMF, bo + (size_t)l*DIMF,
            Wg1 + (size_t)l*3*DIMF,
            ln2g + (size_t)l*DIMF, ln2b + (size_t)l*DIMF,
            W1 + (size_t)l*DIMF*4*DIMF, b1 + (size_t)l*4*DIMF,
            W2 + (size_t)l*4*DIMF*DIMF, b2 + (size_t)l*DIMF,
            Wg2 + (size_t)l*3*DIMF);
    }

    k_final<<<1, 512>>>(Wlin, blin, (float*)d_out);
}